// round 7
// baseline (speedup 1.0000x reference)
#include <cuda_runtime.h>

#define DT 0.025f
#define NTHREADS 128
#define ROW 13
#define BLK_FLOATS (NTHREADS * ROW)          // 1664
#define WARP_VEC4  (32 * ROW / 4)            // 104 float4 per warp slice

__global__ void __launch_bounds__(NTHREADS, 8)
get_next_states_kernel(const float* __restrict__ params,
                       const float* __restrict__ states,
                       const float* __restrict__ actions,
                       const float* __restrict__ foot_pos,
                       const int* __restrict__ foot_contacts,
                       float* __restrict__ out,
                       int n)
{
    __shared__ float sbuf[BLK_FLOATS];

    int tid  = threadIdx.x;
    int lane = tid & 31;
    int wrp  = tid >> 5;
    int blockBase = blockIdx.x * NTHREADS;
    int i = blockBase + tid;
    bool fullBlock = (blockBase + NTHREADS) <= n;

    // ---- per-kernel constants from params (broadcast L1 hits) ----
    float p0 = __ldg(params + 0);
    float p1 = __ldg(params + 1);
    float p2 = __ldg(params + 2);
    float p3 = __ldg(params + 3);
    float p4 = __ldg(params + 4);
    float p5 = __ldg(params + 5);
    float p6 = __ldg(params + 6);

    // ---- issue independent per-row loads early ----
    float4 aA, aB, aC, fA, fB, fC;
    int4 fc4 = make_int4(0, 0, 0, 0);
    if (i < n) {
        const float4* a4 = (const float4*)(actions  + (size_t)i * 12);
        const float4* f4 = (const float4*)(foot_pos + (size_t)i * 12);
        aA = a4[0]; aB = a4[1]; aC = a4[2];
        fA = f4[0]; fB = f4[1]; fC = f4[2];
        fc4 = *(const int4*)(foot_contacts + (size_t)i * 4);
    } else {
        aA = aB = aC = fA = fB = fC = make_float4(0.f, 0.f, 0.f, 0.f);
    }

    // ---- states: warp-autonomous coalesced staging (no block barrier) ----
    float s0, s1, s2, s3, s4, s5, s6, s7, s8, s9, s10, s11, s12;
    if (fullBlock) {
        const float4* src = (const float4*)(states + (size_t)blockBase * ROW) + wrp * WARP_VEC4;
        float4* dst = (float4*)sbuf + wrp * WARP_VEC4;
        #pragma unroll
        for (int j = 0; j < 4; j++) {
            int idx = lane + j * 32;
            if (idx < WARP_VEC4) dst[idx] = src[idx];
        }
        __syncwarp();
        const float* s = sbuf + tid * ROW;
        s0 = s[0];  s1 = s[1];  s2 = s[2];  s3 = s[3];  s4 = s[4];
        s5 = s[5];  s6 = s[6];  s7 = s[7];  s8 = s[8];  s9 = s[9];
        s10 = s[10]; s11 = s[11]; s12 = s[12];
    } else {
        // tail block: direct scalar loads, no barriers
        const float* s = states + (size_t)i * ROW;
        bool v = i < n;
        s0 = v ? s[0] : 0.f;  s1 = v ? s[1] : 0.f;  s2 = v ? s[2] : 0.f;
        s3 = v ? s[3] : 0.f;  s4 = v ? s[4] : 0.f;  s5 = v ? s[5] : 0.f;
        s6 = v ? s[6] : 0.f;  s7 = v ? s[7] : 0.f;  s8 = v ? s[8] : 0.f;
        s9 = v ? s[9] : 0.f;  s10 = v ? s[10] : 0.f; s11 = v ? s[11] : 0.f;
        s12 = v ? s[12] : 0.f;
    }

    // ---- constants: inertia inverse (recomputed per thread, ALU-cheap) ----
    float inv_mass = 1.0f / p0;
    float I00 = p1*p1 + 1e-5f;
    float I01 = p1*p2 + 1e-5f;
    float I02 = p1*p4 + 1e-5f;
    float I11 = p2*p2 + p3*p3 + 1e-5f;
    float I12 = p2*p4 + p3*p5 + 1e-5f;
    float I22 = p4*p4 + p5*p5 + p6*p6 + 1e-5f;
    float c00 = I11*I22 - I12*I12;
    float c01 = I02*I12 - I01*I22;
    float c02 = I01*I12 - I02*I11;
    float det = I00*c00 + I01*c01 + I02*c02;
    float invdet = 1.0f / det;
    float iI00 = c00 * invdet;
    float iI01 = c01 * invdet;
    float iI02 = c02 * invdet;
    float iI11 = (I00*I22 - I02*I02) * invdet;
    float iI12 = (I02*I01 - I00*I12) * invdet;
    float iI22 = (I00*I11 - I01*I01) * invdet;

    // Hybrid precision trig: pitch precise (1/cp amplification), roll/yaw MUFU
    float sr, cr, sp, cp, sy, cy;
    __sincosf(s0, &sr, &cr);
    sincosf(s1, &sp, &cp);
    __sincosf(s2, &sy, &cy);

    float R00 = cy*cp, R01 = cy*sp*sr - sy*cr, R02 = cy*sp*cr + sy*sr;
    float R10 = sy*cp, R11 = sy*sp*sr + cy*cr, R12 = sy*sp*cr - cy*sr;
    float R20 = -sp,   R21 = cp*sr,            R22 = cp*cr;
    float rcp_cp = 1.0f / cp;

    float ax[4] = { aA.x, aA.w, aB.z, aC.y };
    float ay[4] = { aA.y, aB.x, aB.w, aC.z };
    float az[4] = { aA.z, aB.y, aC.x, aC.w };
    float px[4] = { fA.x, fA.w, fB.z, fC.y };
    float py[4] = { fA.y, fB.x, fB.w, fC.z };
    float pz[4] = { fA.z, fB.y, fC.x, fC.w };
    float fcw[4] = { (float)(fc4.x != 0), (float)(fc4.y != 0),
                     (float)(fc4.z != 0), (float)(fc4.w != 0) };

    // w = sum_f fc * (foot_world_f x a_f); F = sum_f fc * a_f
    float wx = 0.f, wy = 0.f, wz = 0.f;
    float Fx = 0.f, Fy = 0.f, Fz = 0.f;
    #pragma unroll
    for (int f = 0; f < 4; f++) {
        float vx = R00*px[f] + R01*py[f] + R02*pz[f];
        float vy = R10*px[f] + R11*py[f] + R12*pz[f];
        float vz = R20*px[f] + R21*py[f] + R22*pz[f];
        wx += fcw[f] * (vy*az[f] - vz*ay[f]);
        wy += fcw[f] * (vz*ax[f] - vx*az[f]);
        wz += fcw[f] * (vx*ay[f] - vy*ax[f]);
        Fx += fcw[f] * ax[f];
        Fy += fcw[f] * ay[f];
        Fz += fcw[f] * az[f];
    }

    // t = R * invI * R^T * w
    float ux = R00*wx + R10*wy + R20*wz;
    float uy = R01*wx + R11*wy + R21*wz;
    float uz = R02*wx + R12*wy + R22*wz;
    float vx = iI00*ux + iI01*uy + iI02*uz;
    float vy = iI01*ux + iI11*uy + iI12*uz;
    float vz = iI02*ux + iI12*uy + iI22*uz;
    float tx = R00*vx + R01*vy + R02*vz;
    float ty = R10*vx + R11*vy + R12*vz;
    float tz = R20*vx + R21*vy + R22*vz;

    float m0 = cy*s6 + sy*s7;
    float o0  = s0 + DT * (m0 * rcp_cp);
    float o1  = s1 + DT * (cy*s7 - sy*s6);
    float o2  = s2 + DT * (m0 * sp * rcp_cp + s8);
    float o3  = s3 + DT * s9;
    float o4  = s4 + DT * s10;
    float o5  = s5 + DT * s11;
    float o6  = s6 + DT * tx;
    float o7  = s7 + DT * ty;
    float o8  = s8 + DT * tz;
    float o9  = s9  + DT * inv_mass * Fx;
    float o10 = s10 + DT * inv_mass * Fy;
    float o11 = s11 + DT * (inv_mass * Fz + s12);
    float o12 = s12;

    if (fullBlock) {
        // warp-autonomous store staging: reuse own warp's slice
        float* w13 = sbuf + tid * ROW;
        w13[0] = o0;  w13[1] = o1;  w13[2] = o2;  w13[3] = o3;  w13[4] = o4;
        w13[5] = o5;  w13[6] = o6;  w13[7] = o7;  w13[8] = o8;  w13[9] = o9;
        w13[10] = o10; w13[11] = o11; w13[12] = o12;
        __syncwarp();
        float4* dst = (float4*)(out + (size_t)blockBase * ROW) + wrp * WARP_VEC4;
        const float4* src = (const float4*)sbuf + wrp * WARP_VEC4;
        #pragma unroll
        for (int j = 0; j < 4; j++) {
            int idx = lane + j * 32;
            if (idx < WARP_VEC4) dst[idx] = src[idx];
        }
    } else if (i < n) {
        float* o = out + (size_t)i * ROW;
        o[0] = o0;  o[1] = o1;  o[2] = o2;  o[3] = o3;  o[4] = o4;
        o[5] = o5;  o[6] = o6;  o[7] = o7;  o[8] = o8;  o[9] = o9;
        o[10] = o10; o[11] = o11; o[12] = o12;
    }
}

extern "C" void kernel_launch(void* const* d_in, const int* in_sizes, int n_in,
                              void* d_out, int out_size) {
    const float* params   = (const float*)d_in[0];
    const float* states   = (const float*)d_in[1];
    const float* actions  = (const float*)d_in[2];
    const float* foot_pos = (const float*)d_in[3];
    const int*   foot_contacts = (const int*)d_in[4];
    float* out = (float*)d_out;

    int n = in_sizes[1] / 13;
    int blocks = (n + NTHREADS - 1) / NTHREADS;
    get_next_states_kernel<<<blocks, NTHREADS>>>(params, states, actions,
                                                 foot_pos, foot_contacts, out, n);
}